// round 13
// baseline (speedup 1.0000x reference)
#include <cuda_runtime.h>
#include <math.h>
#include <stdint.h>

// ---------------- problem constants ----------------
#define NN    3000          // nodes
#define NP    3072          // padded nodes (24*128)
#define NF    2             // input feats
#define NU    64            // units
#define NB    16            // batch
#define NC    66            // C = NF + NU
#define FP    1152          // padded feature rows (72*16, 6*192)
#define KP    336           // padded gconv K (330 -> 21*16)
#define HXST  (NN*NU)
#define INST  (NN*NF)

// mma tiling
#define BM 128
#define BN 192
#define BK 16
#define NKT (NP/BK)         // 192
#define NST 3               // pipeline stages
#define ASTR 20             // smem row stride (floats), conflict-free for ldmatrix
#define SMEM_BYTES (NST*(BM+BN)*ASTR*4)   // 76800

// ---------------- static device buffers ----------------
// X feature matrices are stored TRANSPOSED: [FP][NP] (feature-major).
__device__ float g_S0[(size_t)NP*NP];        // tf32-rounded fp32, row-major [m][k]
__device__ float g_S1[(size_t)NP*NP];
__device__ float g_X0 [(size_t)FP*NP];
__device__ float g_X1a[(size_t)FP*NP];
__device__ float g_X2a[(size_t)FP*NP];
__device__ float g_X1b[(size_t)FP*NP];
__device__ float g_X2b[(size_t)FP*NP];
__device__ float g_XS[(size_t)NB*NN*KP];
__device__ float g_u [(size_t)NB*NN*NU];
__device__ float g_Wg[KP*128];
__device__ float g_Wc[KP*64];
__device__ float g_dinv_row[NP];
__device__ float g_dinv_col[NP];
__device__ float g_colpart[24*NP];

// ---------------- helpers ----------------
__device__ __forceinline__ float rtf32(float x) {
    uint32_t u;
    asm("cvt.rna.tf32.f32 %0, %1;" : "=r"(u) : "f"(x));
    return __uint_as_float(u);
}
__device__ __forceinline__ uint32_t smem_u32(const void* p) {
    uint32_t a;
    asm("{ .reg .u64 t; cvta.to.shared.u64 t, %1; cvt.u32.u64 %0, t; }"
        : "=r"(a) : "l"(p));
    return a;
}
#define CPA16P(dst, src) \
    asm volatile("cp.async.cg.shared.global [%0], [%1], 16;" \
                 :: "r"(smem_u32(dst)), "l"(src))
#define CP_COMMIT() asm volatile("cp.async.commit_group;" ::: "memory")
#define CP_WAIT(n)  asm volatile("cp.async.wait_group %0;" :: "n"(n) : "memory")

#define LDSM4(r0, r1, r2, r3, addr) \
    asm volatile("ldmatrix.sync.aligned.m8n8.x4.shared.b16 {%0,%1,%2,%3}, [%4];" \
        : "=r"(r0), "=r"(r1), "=r"(r2), "=r"(r3) : "r"(addr))

#define MMA_TF32(d, a, b) \
    asm volatile( \
        "mma.sync.aligned.m16n8k8.row.col.f32.tf32.tf32.f32 " \
        "{%0,%1,%2,%3}, {%4,%5,%6,%7}, {%8,%9}, {%0,%1,%2,%3};" \
        : "+f"((d)[0]), "+f"((d)[1]), "+f"((d)[2]), "+f"((d)[3]) \
        : "r"((a)[0]), "r"((a)[1]), "r"((a)[2]), "r"((a)[3]), \
          "r"((b)[0]), "r"((b)[1]))

// packed fp32x2 (projection GEMM)
__device__ __forceinline__ unsigned long long pk2(float lo, float hi) {
    unsigned long long r;
    asm("mov.b64 %0, {%1, %2};" : "=l"(r) : "f"(lo), "f"(hi));
    return r;
}
__device__ __forceinline__ void upk2(unsigned long long v, float& lo, float& hi) {
    asm("mov.b64 {%0, %1}, %2;" : "=f"(lo), "=f"(hi) : "l"(v));
}
__device__ __forceinline__ unsigned long long fma2(unsigned long long a,
                                                   unsigned long long b,
                                                   unsigned long long c) {
    unsigned long long d;
    asm("fma.rn.f32x2 %0, %1, %2, %3;" : "=l"(d) : "l"(a), "l"(b), "l"(c));
    return d;
}

// ---------------- degree kernels ----------------
__global__ void deg_row_kernel(const float* __restrict__ adj) {
    __shared__ float red[256];
    int row = blockIdx.x;
    int tid = threadIdx.x;
    if (row >= NN) { if (tid == 0) g_dinv_row[row] = 0.f; return; }
    float s = 0.f;
    for (int c = tid; c < NN; c += 256) s += adj[(size_t)row*NN + c];
    red[tid] = s; __syncthreads();
    for (int st = 128; st > 0; st >>= 1) {
        if (tid < st) red[tid] += red[tid+st];
        __syncthreads();
    }
    if (tid == 0) {
        float d = red[0];
        g_dinv_row[row] = (d > 0.f) ? 1.f/d : 0.f;
    }
}

__global__ void deg_col1_kernel(const float* __restrict__ adj) {
    int c = blockIdx.x*256 + threadIdx.x;
    int chunk = blockIdx.y;
    if (c >= NN) { if (c < NP) g_colpart[chunk*NP + c] = 0.f; return; }
    int r0 = chunk*125;
    float s = 0.f;
    for (int r = r0; r < r0 + 125; r++) s += adj[(size_t)r*NN + c];
    g_colpart[chunk*NP + c] = s;
}

__global__ void deg_col2_kernel() {
    int c = blockIdx.x*256 + threadIdx.x;
    if (c >= NP) return;
    if (c >= NN) { g_dinv_col[c] = 0.f; return; }
    float s = 0.f;
    #pragma unroll
    for (int k = 0; k < 24; k++) s += g_colpart[k*NP + c];
    g_dinv_col[c] = (s > 0.f) ? 1.f/s : 0.f;
}

// ---------------- build S0/S1 (tf32-rounded fp32, pads zero) ----------------
__global__ void build_S_kernel(const float* __restrict__ adj) {
    __shared__ float sm[32][33];
    int tx = threadIdx.x, ty = threadIdx.y;
    int i0 = blockIdx.y*32, j0 = blockIdx.x*32;
    #pragma unroll
    for (int q = 0; q < 4; q++) {
        int ii = q*8 + ty;
        int gi = i0 + ii, gj = j0 + tx;
        float v = (gi < NN && gj < NN) ? adj[(size_t)gi*NN + gj] : 0.f;
        sm[ii][tx] = v;
        g_S1[(size_t)gi*NP + gj] = rtf32(v * g_dinv_col[gj]);
    }
    __syncthreads();
    #pragma unroll
    for (int q = 0; q < 4; q++) {
        int jj = q*8 + ty;
        g_S0[(size_t)(j0+jj)*NP + (i0+tx)] = rtf32(sm[tx][jj] * g_dinv_row[i0+tx]);
    }
}

// ---------------- build X0 transposed [FP][NP] (tf32-rounded), pads zero ----------------
__global__ void build_x0_kernel(const float* __restrict__ in,
                                const float* __restrict__ hx) {
    int id = blockIdx.x*256 + threadIdx.x;     // FP*NP / 256 exact
    int f = id / NP, n = id % NP;
    int c = f >> 4, b = f & 15;
    float v = 0.f;
    if (n < NN && c < NC) {
        v = (c < NF) ? in[(size_t)b*INST + n*NF + c]
                     : hx[(size_t)b*HXST + n*NU + (c - NF)];
    }
    g_X0[id] = rtf32(v);
}

// ---------------- pad weights ----------------
__global__ void pad_W_kernel(const float* __restrict__ Wg,
                             const float* __restrict__ Wc) {
    int id = blockIdx.x*256 + threadIdx.x;
    if (id < KP*128) {
        int k = id / 128, j = id % 128;
        g_Wg[id] = (k < 330) ? Wg[k*128 + j] : 0.f;
    } else {
        int id2 = id - KP*128;
        if (id2 < KP*64) {
            int k = id2 / 64, j = id2 % 64;
            g_Wc[id2] = (k < 330) ? Wc[k*64 + j] : 0.f;
        }
    }
}

// ---------------- materialize XS from transposed buffers ----------------
__global__ void materialize_xs_kernel() {
    int id = blockIdx.x*256 + threadIdx.x;
    if (id >= NB*NC*NN) return;
    int n = id % NN;
    int t = id / NN;
    int c = t % NC;
    int b = t / NC;
    size_t src = (size_t)(c*16 + b)*NP + n;
    size_t row = ((size_t)b*NN + n)*KP + c*5;
    g_XS[row+0] = g_X0 [src];
    g_XS[row+1] = g_X1a[src];
    g_XS[row+2] = g_X2a[src];
    g_XS[row+3] = g_X1b[src];
    g_XS[row+4] = g_X2b[src];
}

// ---------------- tf32 mma GEMM, 128x192 tiles, 3-stage cp.async ----------------
// C^T = (S @ X)^T with X transposed [n(feature)][k(node)].
// A = S row-major [m][k]; B = Xt [n][k]; output written transposed [n][m].
// MODE1: C = 2*S@X - SUB (SUB transposed layout too).
template<int MODE>
__global__ __launch_bounds__(256, 1)
void mma_tf32(const float* __restrict__ A,
              const float* __restrict__ B,
              float* __restrict__ C,
              const float* __restrict__ SUB)
{
    extern __shared__ __align__(16) float smem_all[];
    float (*As)[BM][ASTR] = reinterpret_cast<float (*)[BM][ASTR]>(smem_all);
    float (*Bs)[BN][ASTR] = reinterpret_cast<float (*)[BN][ASTR]>(smem_all + NST*BM*ASTR);

    int tid  = threadIdx.x;
    int wid  = tid >> 5, lane = tid & 31;
    int warp_m = (wid >> 2) * 64;       // 2 m-groups
    int warp_n = (wid & 3) * 48;        // 4 n-groups
    int rowbase = blockIdx.y * BM;
    int colbase = blockIdx.x * BN;
    int g = lane >> 2, r4 = lane & 3;

    // ldmatrix lane-address components
    int mq = lane >> 3, r8 = lane & 7;
    uint32_t sA = smem_u32(smem_all);
    uint32_t sB = sA + NST*BM*ASTR*4;
    uint32_t offA = ((warp_m + (mq & 1)*8 + r8)*ASTR + (mq >> 1)*4) * 4;
    uint32_t offB = ((warp_n + (mq >> 1)*8 + r8)*ASTR + (mq & 1)*4) * 4;

    float acc[4][6][4];
    #pragma unroll
    for (int mt = 0; mt < 4; mt++)
        #pragma unroll
        for (int nt = 0; nt < 6; nt++)
            #pragma unroll
            for (int q = 0; q < 4; q++) acc[mt][nt][q] = 0.f;

    #define LOAD_TILE(kt, buf)                                                 \
    do {                                                                       \
        int k0 = (kt) * BK;                                                    \
        _Pragma("unroll")                                                      \
        for (int i = 0; i < 2; i++) {                                          \
            int idx = tid + i*256;                                             \
            int rr = idx >> 2, kc = (idx & 3) * 4;                             \
            CPA16P(&As[buf][rr][kc],                                           \
                   &A[(size_t)(rowbase + rr)*NP + k0 + kc]);                   \
        }                                                                      \
        _Pragma("unroll")                                                      \
        for (int i = 0; i < 3; i++) {                                          \
            int idx = tid + i*256;                                             \
            int rr = idx >> 2, kc = (idx & 3) * 4;                             \
            CPA16P(&Bs[buf][rr][kc],                                           \
                   &B[(size_t)(colbase + rr)*NP + k0 + kc]);                   \
        }                                                                      \
    } while (0)

    LOAD_TILE(0, 0);
    CP_COMMIT();
    LOAD_TILE(1, 1);
    CP_COMMIT();

    for (int kt = 0; kt < NKT; kt++) {
        int buf = kt % NST;
        if (kt < NKT - 1) { CP_WAIT(1); } else { CP_WAIT(0); }
        __syncthreads();

        if (kt + 2 < NKT) {
            LOAD_TILE(kt + 2, (kt + 2) % NST);
            CP_COMMIT();
        }

        uint32_t bA = sA + buf*(BM*ASTR*4);
        uint32_t bB = sB + buf*(BN*ASTR*4);
        #pragma unroll
        for (int ks = 0; ks < 2; ks++) {
            uint32_t af[4][4];
            uint32_t bf[6][2];
            #pragma unroll
            for (int mt = 0; mt < 4; mt++)
                LDSM4(af[mt][0], af[mt][1], af[mt][2], af[mt][3],
                      bA + mt*(16*ASTR*4) + ks*32 + offA);
            #pragma unroll
            for (int p = 0; p < 3; p++)
                LDSM4(bf[2*p][0], bf[2*p][1], bf[2*p+1][0], bf[2*p+1][1],
                      bB + p*(16*ASTR*4) + ks*32 + offB);
            #pragma unroll
            for (int mt = 0; mt < 4; mt++)
                #pragma unroll
                for (int nt = 0; nt < 6; nt++)
                    MMA_TF32(acc[mt][nt], af[mt], bf[nt]);
        }
        __syncthreads();
    }
    #undef LOAD_TILE

    // epilogue: 4 phases; transpose 48 n-rows at a time through smem
    float (*st)[132] = reinterpret_cast<float (*)[132]>(smem_all);
    #pragma unroll
    for (int h = 0; h < 4; h++) {
        if ((wid & 3) == h) {
            #pragma unroll
            for (int mt = 0; mt < 4; mt++) {
                int m0 = warp_m + mt*16 + g;
                #pragma unroll
                for (int nt = 0; nt < 6; nt++) {
                    int n0 = nt*8 + r4*2;
                    st[n0  ][m0  ] = acc[mt][nt][0];
                    st[n0+1][m0  ] = acc[mt][nt][1];
                    st[n0  ][m0+8] = acc[mt][nt][2];
                    st[n0+1][m0+8] = acc[mt][nt][3];
                }
            }
        }
        __syncthreads();
        #pragma unroll
        for (int i = 0; i < 6; i++) {
            int idx = tid + i*256;            // 0..1535
            int nn = idx >> 5;                // 0..47
            int mm = (idx & 31) * 4;
            float4 v = *reinterpret_cast<float4*>(&st[nn][mm]);
            size_t off = (size_t)(colbase + h*48 + nn)*NP + rowbase + mm;
            if (MODE == 1) {
                float4 s = *reinterpret_cast<const float4*>(&SUB[off]);
                v.x = 2.f*v.x - s.x; v.y = 2.f*v.y - s.y;
                v.z = 2.f*v.z - s.z; v.w = 2.f*v.w - s.w;
            }
            v.x = rtf32(v.x); v.y = rtf32(v.y);
            v.z = rtf32(v.z); v.w = rtf32(v.w);
            *reinterpret_cast<float4*>(&C[off]) = v;
        }
        __syncthreads();
    }
}

// ---------------- projection GEMM (fp32x2 FFMA) with fused epilogues ----------------
// MODE 2: gate (sigmoid; col<64 -> r*hx into X0t state rows; else -> u buffer)
// MODE 3: cand (tanh; out = u*hx + (1-u)*c)
#define GBM 128
#define GBN 64
#define GBK 16

template<int MODE>
__global__ __launch_bounds__(128)
void gemm128(const float* __restrict__ A, int lda,
             const float* __restrict__ B, int ldb,
             int K,
             const float* __restrict__ bias,
             const float* __restrict__ hx,
             float* __restrict__ aux,
             float* __restrict__ out)
{
    __shared__ __align__(16) float As[GBK][GBM];
    __shared__ __align__(16) float Bs[GBK][GBN];

    int tid = threadIdx.x;
    int tx = tid & 7;
    int ty = tid >> 3;
    int rowbase = blockIdx.y * GBM;
    int colbase = blockIdx.x * GBN;

    unsigned long long acc[4][8];
    #pragma unroll
    for (int i = 0; i < 4; i++)
        #pragma unroll
        for (int j = 0; j < 8; j++) acc[i][j] = 0ULL;

    int ktiles = K / GBK;
    for (int kt = 0; kt < ktiles; kt++) {
        int k0 = kt * GBK;
        #pragma unroll
        for (int i = 0; i < 4; i++) {
            int q  = tid + i*128;
            int r  = q >> 2;
            int kc = (q & 3) * 4;
            float4 v = *reinterpret_cast<const float4*>(
                &A[(size_t)(rowbase + r)*lda + k0 + kc]);
            As[kc+0][r] = v.x; As[kc+1][r] = v.y;
            As[kc+2][r] = v.z; As[kc+3][r] = v.w;
        }
        #pragma unroll
        for (int i = 0; i < 2; i++) {
            int q  = tid + i*128;
            int kr = q >> 4;
            int c4 = (q & 15) * 4;
            *reinterpret_cast<float4*>(&Bs[kr][c4]) =
                *reinterpret_cast<const float4*>(
                    &B[(size_t)(k0 + kr)*ldb + colbase + c4]);
        }
        __syncthreads();
        #pragma unroll
        for (int k = 0; k < GBK; k++) {
            const unsigned long long* ap =
                reinterpret_cast<const unsigned long long*>(&As[k][ty*8]);
            unsigned long long a2[4];
            a2[0]=ap[0]; a2[1]=ap[1]; a2[2]=ap[2]; a2[3]=ap[3];
            float4 b0 = *reinterpret_cast<const float4*>(&Bs[k][tx*8]);
            float4 b1 = *reinterpret_cast<const float4*>(&Bs[k][tx*8+4]);
            unsigned long long bs[8];
            bs[0]=pk2(b0.x,b0.x); bs[1]=pk2(b0.y,b0.y);
            bs[2]=pk2(b0.z,b0.z); bs[3]=pk2(b0.w,b0.w);
            bs[4]=pk2(b1.x,b1.x); bs[5]=pk2(b1.y,b1.y);
            bs[6]=pk2(b1.z,b1.z); bs[7]=pk2(b1.w,b1.w);
            #pragma unroll
            for (int i2 = 0; i2 < 4; i2++)
                #pragma unroll
                for (int j = 0; j < 8; j++)
                    acc[i2][j] = fma2(a2[i2], bs[j], acc[i2][j]);
        }
        __syncthreads();
    }

    int cc = colbase + tx*8;
    #pragma unroll
    for (int i2 = 0; i2 < 4; i2++) {
        #pragma unroll
        for (int j = 0; j < 8; j++) {
            float lo, hi; upk2(acc[i2][j], lo, hi);
            int col = cc + j;
            #pragma unroll
            for (int h = 0; h < 2; h++) {
                int row = rowbase + ty*8 + 2*i2 + h;
                float v = h ? hi : lo;
                int bb = row / NN;
                int n  = row - bb*NN;
                if (MODE == 2) {
                    float s = 1.f/(1.f + expf(-(v + bias[col])));
                    if (col < NU) {
                        // r*hx -> transposed X0 state row (NF+col)*16+bb
                        out[(size_t)((NF + col)*16 + bb)*NP + n] =
                            rtf32(s * hx[(size_t)bb*HXST + n*NU + col]);
                    } else {
                        aux[(size_t)bb*HXST + n*NU + (col - NU)] = s;
                    }
                } else {
                    float cand = tanhf(v + bias[col]);
                    size_t idx = (size_t)bb*HXST + n*NU + col;
                    float uu = aux[idx];
                    out[idx] = uu*hx[idx] + (1.f - uu)*cand;
                }
            }
        }
    }
}

// ---------------- launcher ----------------
extern "C" void kernel_launch(void* const* d_in, const int* in_sizes, int n_in,
                              void* d_out, int out_size) {
    const float* in_inputs = (const float*)d_in[0];
    const float* in_hx     = (const float*)d_in[1];
    const float* in_adj    = (const float*)d_in[2];
    const float* in_Wg     = (const float*)d_in[3];
    const float* in_bg     = (const float*)d_in[4];
    const float* in_Wc     = (const float*)d_in[5];
    const float* in_bc     = (const float*)d_in[6];
    float* outp = (float*)d_out;

    float *pS0, *pS1, *pX0, *pX1a, *pX2a, *pX1b, *pX2b, *pXS, *pU, *pWg, *pWc;
    cudaGetSymbolAddress((void**)&pS0,  g_S0);
    cudaGetSymbolAddress((void**)&pS1,  g_S1);
    cudaGetSymbolAddress((void**)&pX0,  g_X0);
    cudaGetSymbolAddress((void**)&pX1a, g_X1a);
    cudaGetSymbolAddress((void**)&pX2a, g_X2a);
    cudaGetSymbolAddress((void**)&pX1b, g_X1b);
    cudaGetSymbolAddress((void**)&pX2b, g_X2b);
    cudaGetSymbolAddress((void**)&pXS,  g_XS);
    cudaGetSymbolAddress((void**)&pU,   g_u);
    cudaGetSymbolAddress((void**)&pWg,  g_Wg);
    cudaGetSymbolAddress((void**)&pWc,  g_Wc);

    cudaFuncSetAttribute(mma_tf32<0>,
        cudaFuncAttributeMaxDynamicSharedMemorySize, SMEM_BYTES);
    cudaFuncSetAttribute(mma_tf32<1>,
        cudaFuncAttributeMaxDynamicSharedMemorySize, SMEM_BYTES);

    // prep
    deg_row_kernel<<<NP, 256>>>(in_adj);
    deg_col1_kernel<<<dim3(12, 24), 256>>>(in_adj);
    deg_col2_kernel<<<12, 256>>>();
    build_S_kernel<<<dim3(96, 96), dim3(32, 8)>>>(in_adj);
    build_x0_kernel<<<(FP*NP)/256, 256>>>(in_inputs, in_hx);
    pad_W_kernel<<<(KP*192 + 255)/256, 256>>>(in_Wg, in_Wc);

    dim3 gG(FP/BN, NP/BM);                 // (6, 24) = 144 blocks
    int xsGrid = (NB*NC*NN + 255)/256;

    // ---- gate gconv ----
    mma_tf32<0><<<gG, 256, SMEM_BYTES>>>(pS0, pX0,  pX1a, nullptr);
    mma_tf32<0><<<gG, 256, SMEM_BYTES>>>(pS1, pX0,  pX1b, nullptr);
    mma_tf32<1><<<gG, 256, SMEM_BYTES>>>(pS0, pX1a, pX2a, pX0);
    mma_tf32<1><<<gG, 256, SMEM_BYTES>>>(pS1, pX1b, pX2b, pX0);
    materialize_xs_kernel<<<xsGrid, 256>>>();

    // gate projection: sigmoid; writes r*hx into X0t state rows, u into g_u
    gemm128<2><<<dim3(2, (NB*NN)/GBM), 128>>>(pXS, KP, pWg, 128, KP,
                                              in_bg, in_hx, pU, pX0);

    // ---- candidate gconv (X0t now holds [inputs, r*hx]) ----
    mma_tf32<0><<<gG, 256, SMEM_BYTES>>>(pS0, pX0,  pX1a, nullptr);
    mma_tf32<0><<<gG, 256, SMEM_BYTES>>>(pS1, pX0,  pX1b, nullptr);
    mma_tf32<1><<<gG, 256, SMEM_BYTES>>>(pS0, pX1a, pX2a, pX0);
    mma_tf32<1><<<gG, 256, SMEM_BYTES>>>(pS1, pX1b, pX2b, pX0);
    materialize_xs_kernel<<<xsGrid, 256>>>();

    // candidate projection + tanh + GRU combine -> d_out
    gemm128<3><<<dim3(1, (NB*NN)/GBM), 128>>>(pXS, KP, pWc, 64, KP,
                                              in_bc, in_hx, pU, outp);
}

// round 14
// speedup vs baseline: 1.2020x; 1.2020x over previous
#include <cuda_runtime.h>
#include <math.h>
#include <stdint.h>

// ---------------- problem constants ----------------
#define NN    3000          // nodes
#define NP    3072          // padded nodes (24*128)
#define NF    2             // input feats
#define NU    64            // units
#define NB    16            // batch
#define NC    66            // C = NF + NU
#define FP    1152          // padded feature rows (72*16, 9*128)
#define KP    336           // padded gconv K (330 -> 21*16)
#define HXST  (NN*NU)
#define INST  (NN*NF)

// mma tiling (gconv)
#define BM 128
#define BN 128
#define BK 16
#define NKT (NP/BK)         // 192
#define ASTR 20             // smem row stride (floats), conflict-free for ldmatrix

// ---------------- static device buffers ----------------
// X feature matrices are stored TRANSPOSED: [FP][NP] (feature-major).
__device__ float g_S0[(size_t)NP*NP];        // tf32-rounded fp32, row-major [m][k]
__device__ float g_S1[(size_t)NP*NP];
__device__ float g_X0 [(size_t)FP*NP];
__device__ float g_X1a[(size_t)FP*NP];
__device__ float g_X2a[(size_t)FP*NP];
__device__ float g_X1b[(size_t)FP*NP];
__device__ float g_X2b[(size_t)FP*NP];
__device__ float g_XS[(size_t)NB*NN*KP];
__device__ float g_u [(size_t)NB*NN*NU];
__device__ float g_Wgt[128*KP];              // W_gate^T [128][KP], tf32-rounded
__device__ float g_Wct[64*KP];               // W_cand^T [64][KP]
__device__ float g_dinv_row[NP];
__device__ float g_dinv_col[NP];
__device__ float g_colpart[24*NP];

// ---------------- helpers ----------------
__device__ __forceinline__ float rtf32(float x) {
    uint32_t u;
    asm("cvt.rna.tf32.f32 %0, %1;" : "=r"(u) : "f"(x));
    return __uint_as_float(u);
}
__device__ __forceinline__ uint32_t smem_u32(const void* p) {
    uint32_t a;
    asm("{ .reg .u64 t; cvta.to.shared.u64 t, %1; cvt.u32.u64 %0, t; }"
        : "=r"(a) : "l"(p));
    return a;
}
#define CPA16P(dst, src) \
    asm volatile("cp.async.cg.shared.global [%0], [%1], 16;" \
                 :: "r"(smem_u32(dst)), "l"(src))
#define CP_COMMIT() asm volatile("cp.async.commit_group;" ::: "memory")
#define CP_WAIT(n)  asm volatile("cp.async.wait_group %0;" :: "n"(n) : "memory")

#define LDSM4(r0, r1, r2, r3, addr) \
    asm volatile("ldmatrix.sync.aligned.m8n8.x4.shared.b16 {%0,%1,%2,%3}, [%4];" \
        : "=r"(r0), "=r"(r1), "=r"(r2), "=r"(r3) : "r"(addr))

#define MMA_TF32(d, a, b) \
    asm volatile( \
        "mma.sync.aligned.m16n8k8.row.col.f32.tf32.tf32.f32 " \
        "{%0,%1,%2,%3}, {%4,%5,%6,%7}, {%8,%9}, {%0,%1,%2,%3};" \
        : "+f"((d)[0]), "+f"((d)[1]), "+f"((d)[2]), "+f"((d)[3]) \
        : "r"((a)[0]), "r"((a)[1]), "r"((a)[2]), "r"((a)[3]), \
          "r"((b)[0]), "r"((b)[1]))

// ---------------- degree kernels ----------------
__global__ void deg_row_kernel(const float* __restrict__ adj) {
    __shared__ float red[256];
    int row = blockIdx.x;
    int tid = threadIdx.x;
    if (row >= NN) { if (tid == 0) g_dinv_row[row] = 0.f; return; }
    float s = 0.f;
    for (int c = tid; c < NN; c += 256) s += adj[(size_t)row*NN + c];
    red[tid] = s; __syncthreads();
    for (int st = 128; st > 0; st >>= 1) {
        if (tid < st) red[tid] += red[tid+st];
        __syncthreads();
    }
    if (tid == 0) {
        float d = red[0];
        g_dinv_row[row] = (d > 0.f) ? 1.f/d : 0.f;
    }
}

__global__ void deg_col1_kernel(const float* __restrict__ adj) {
    int c = blockIdx.x*256 + threadIdx.x;
    int chunk = blockIdx.y;
    if (c >= NN) { if (c < NP) g_colpart[chunk*NP + c] = 0.f; return; }
    int r0 = chunk*125;
    float s = 0.f;
    for (int r = r0; r < r0 + 125; r++) s += adj[(size_t)r*NN + c];
    g_colpart[chunk*NP + c] = s;
}

__global__ void deg_col2_kernel() {
    int c = blockIdx.x*256 + threadIdx.x;
    if (c >= NP) return;
    if (c >= NN) { g_dinv_col[c] = 0.f; return; }
    float s = 0.f;
    #pragma unroll
    for (int k = 0; k < 24; k++) s += g_colpart[k*NP + c];
    g_dinv_col[c] = (s > 0.f) ? 1.f/s : 0.f;
}

// ---------------- build S0/S1 (tf32-rounded fp32, pads zero) ----------------
__global__ void build_S_kernel(const float* __restrict__ adj) {
    __shared__ float sm[32][33];
    int tx = threadIdx.x, ty = threadIdx.y;
    int i0 = blockIdx.y*32, j0 = blockIdx.x*32;
    #pragma unroll
    for (int q = 0; q < 4; q++) {
        int ii = q*8 + ty;
        int gi = i0 + ii, gj = j0 + tx;
        float v = (gi < NN && gj < NN) ? adj[(size_t)gi*NN + gj] : 0.f;
        sm[ii][tx] = v;
        g_S1[(size_t)gi*NP + gj] = rtf32(v * g_dinv_col[gj]);
    }
    __syncthreads();
    #pragma unroll
    for (int q = 0; q < 4; q++) {
        int jj = q*8 + ty;
        g_S0[(size_t)(j0+jj)*NP + (i0+tx)] = rtf32(sm[tx][jj] * g_dinv_row[i0+tx]);
    }
}

// ---------------- build X0 transposed [FP][NP] (tf32-rounded), pads zero ----------------
__global__ void build_x0_kernel(const float* __restrict__ in,
                                const float* __restrict__ hx) {
    int id = blockIdx.x*256 + threadIdx.x;     // FP*NP / 256 exact
    int f = id / NP, n = id % NP;
    int c = f >> 4, b = f & 15;
    float v = 0.f;
    if (n < NN && c < NC) {
        v = (c < NF) ? in[(size_t)b*INST + n*NF + c]
                     : hx[(size_t)b*HXST + n*NU + (c - NF)];
    }
    g_X0[id] = rtf32(v);
}

// ---------------- pad + transpose weights (tf32-rounded) ----------------
__global__ void pad_W_kernel(const float* __restrict__ Wg,
                             const float* __restrict__ Wc) {
    int id = blockIdx.x*256 + threadIdx.x;     // (128+64)*KP / 256 exact
    if (id < 128*KP) {
        int n = id / KP, k = id % KP;
        g_Wgt[id] = (k < 330) ? rtf32(Wg[k*128 + n]) : 0.f;
    } else {
        int id2 = id - 128*KP;
        int n = id2 / KP, k = id2 % KP;
        g_Wct[id2] = (k < 330) ? rtf32(Wc[k*64 + n]) : 0.f;
    }
}

// ---------------- materialize XS from transposed buffers ----------------
// XS pad cols (330..335) never written; zero-init globals + zero W pad rows
// make their contribution exactly 0.
__global__ void materialize_xs_kernel() {
    int id = blockIdx.x*256 + threadIdx.x;
    if (id >= NB*NC*NN) return;
    int n = id % NN;
    int t = id / NN;
    int c = t % NC;
    int b = t / NC;
    size_t src = (size_t)(c*16 + b)*NP + n;
    size_t row = ((size_t)b*NN + n)*KP + c*5;
    g_XS[row+0] = g_X0 [src];
    g_XS[row+1] = g_X1a[src];
    g_XS[row+2] = g_X2a[src];
    g_XS[row+3] = g_X1b[src];
    g_XS[row+4] = g_X2b[src];
}

// ---------------- tf32 mma GEMM with ldmatrix frags (R10-proven mainloop) ----
// z-fused: blockIdx.z selects (A0,B0,C0,SUB0) vs (A1,B1,C1,SUB1).
// C^T = (S @ X)^T with X transposed [n(feature)][k(node)].
// MODE1: C = 2*S@X - SUB (SUB transposed layout too).
template<int MODE>
__global__ __launch_bounds__(128, 2)
void mma_tf32(const float* __restrict__ A0, const float* __restrict__ B0,
              float* __restrict__ C0, const float* __restrict__ SUB0,
              const float* __restrict__ A1, const float* __restrict__ B1,
              float* __restrict__ C1, const float* __restrict__ SUB1)
{
    const float* __restrict__ A   = blockIdx.z ? A1   : A0;
    const float* __restrict__ B   = blockIdx.z ? B1   : B0;
    float*       __restrict__ C   = blockIdx.z ? C1   : C0;
    const float* __restrict__ SUB = blockIdx.z ? SUB1 : SUB0;

    __shared__ __align__(16) float smem_all[2*BM*ASTR + 2*BN*ASTR];
    float (*As)[BM][ASTR] = reinterpret_cast<float (*)[BM][ASTR]>(smem_all);
    float (*Bs)[BN][ASTR] = reinterpret_cast<float (*)[BN][ASTR]>(smem_all + 2*BM*ASTR);

    int tid  = threadIdx.x;
    int wid  = tid >> 5, lane = tid & 31;
    int warp_m = (wid >> 1) * 64;
    int warp_n = (wid & 1) * 64;
    int rowbase = blockIdx.y * BM;
    int colbase = blockIdx.x * BN;
    int g = lane >> 2, r4 = lane & 3;

    int mq = lane >> 3, r8 = lane & 7;
    uint32_t sA = smem_u32(smem_all);
    uint32_t sB = sA + 2*BM*ASTR*4;
    uint32_t offA = ((warp_m + (mq & 1)*8 + r8)*ASTR + (mq >> 1)*4) * 4;
    uint32_t offB = ((warp_n + (mq >> 1)*8 + r8)*ASTR + (mq & 1)*4) * 4;

    float acc[4][8][4];
    #pragma unroll
    for (int mt = 0; mt < 4; mt++)
        #pragma unroll
        for (int nt = 0; nt < 8; nt++)
            #pragma unroll
            for (int q = 0; q < 4; q++) acc[mt][nt][q] = 0.f;

    #define LOAD_TILE(kt, buf)                                                 \
    do {                                                                       \
        int k0 = (kt) * BK;                                                    \
        _Pragma("unroll")                                                      \
        for (int i = 0; i < 4; i++) {                                          \
            int idx = tid + i*128;                                             \
            int rr = idx >> 2, kc = (idx & 3) * 4;                             \
            CPA16P(&As[buf][rr][kc],                                           \
                   &A[(size_t)(rowbase + rr)*NP + k0 + kc]);                   \
        }                                                                      \
        _Pragma("unroll")                                                      \
        for (int i = 0; i < 4; i++) {                                          \
            int idx = tid + i*128;                                             \
            int rr = idx >> 2, kc = (idx & 3) * 4;                             \
            CPA16P(&Bs[buf][rr][kc],                                           \
                   &B[(size_t)(colbase + rr)*NP + k0 + kc]);                   \
        }                                                                      \
    } while (0)

    LOAD_TILE(0, 0);
    CP_COMMIT();

    for (int kt = 0; kt < NKT; kt++) {
        int buf = kt & 1;
        if (kt < NKT - 1) {
            LOAD_TILE(kt + 1, buf ^ 1);
            CP_COMMIT();
            CP_WAIT(1);
        } else {
            CP_WAIT(0);
        }
        __syncthreads();

        uint32_t bA = sA + buf*(BM*ASTR*4);
        uint32_t bB = sB + buf*(BN*ASTR*4);
        #pragma unroll
        for (int ks = 0; ks < 2; ks++) {
            uint32_t af[4][4];
            uint32_t bf[8][2];
            #pragma unroll
            for (int mt = 0; mt < 4; mt++)
                LDSM4(af[mt][0], af[mt][1], af[mt][2], af[mt][3],
                      bA + mt*(16*ASTR*4) + ks*32 + offA);
            #pragma unroll
            for (int p = 0; p < 4; p++)
                LDSM4(bf[2*p][0], bf[2*p][1], bf[2*p+1][0], bf[2*p+1][1],
                      bB + p*(16*ASTR*4) + ks*32 + offB);
            #pragma unroll
            for (int mt = 0; mt < 4; mt++)
                #pragma unroll
                for (int nt = 0; nt < 8; nt++)
                    MMA_TF32(acc[mt][nt], af[mt], bf[nt]);
        }
        __syncthreads();
    }
    #undef LOAD_TILE

    // epilogue: transpose through smem, write C^T[n][m] with float4 stores
    float (*st)[132] = reinterpret_cast<float (*)[132]>(smem_all);
    #pragma unroll
    for (int h = 0; h < 2; h++) {
        __syncthreads();
        if ((wid & 1) == h) {
            #pragma unroll
            for (int mt = 0; mt < 4; mt++) {
                int m0 = warp_m + mt*16 + g;
                #pragma unroll
                for (int nt = 0; nt < 8; nt++) {
                    int n0 = nt*8 + r4*2;
                    st[n0  ][m0  ] = acc[mt][nt][0];
                    st[n0+1][m0  ] = acc[mt][nt][1];
                    st[n0  ][m0+8] = acc[mt][nt][2];
                    st[n0+1][m0+8] = acc[mt][nt][3];
                }
            }
        }
        __syncthreads();
        #pragma unroll
        for (int i = 0; i < 16; i++) {
            int idx = tid + i*128;            // 0..2047
            int nn = idx >> 5;                // 0..63
            int mm = (idx & 31) * 4;
            float4 v = *reinterpret_cast<float4*>(&st[nn][mm]);
            size_t off = (size_t)(colbase + h*64 + nn)*NP + rowbase + mm;
            if (MODE == 1) {
                float4 s = *reinterpret_cast<const float4*>(&SUB[off]);
                v.x = 2.f*v.x - s.x; v.y = 2.f*v.y - s.y;
                v.z = 2.f*v.z - s.z; v.w = 2.f*v.w - s.w;
            }
            v.x = rtf32(v.x); v.y = rtf32(v.y);
            v.z = rtf32(v.z); v.w = rtf32(v.w);
            *reinterpret_cast<float4*>(&C[off]) = v;
        }
    }
}

// ---------------- tf32 mma projection GEMM with fused epilogues ----------------
// A = XS [48000][KP] row-major, Bt = W^T [PBN][KP].
// MODE 2: gate (sigmoid; col<64 -> r*hx into X0t state rows; else -> u buffer)
// MODE 3: cand (tanh; out = u*hx + (1-u)*c)
template<int MODE>
__global__ __launch_bounds__(128, 2)
void mma_proj(const float* __restrict__ A,
              const float* __restrict__ Bt,
              const float* __restrict__ bias,
              const float* __restrict__ hx,
              float* __restrict__ aux,
              float* __restrict__ out)
{
    constexpr int PBN = (MODE == 2) ? 128 : 64;
    constexpr int PMT = (MODE == 2) ? 4 : 2;
    constexpr int NKP = KP/BK;   // 21

    __shared__ __align__(16) float As_[2][128][ASTR];
    __shared__ __align__(16) float Bs_[2][PBN][ASTR];

    int tid = threadIdx.x, wid = tid >> 5, lane = tid & 31;
    int warp_m = (MODE == 2) ? (wid >> 1)*64 : wid*32;
    int warp_n = (MODE == 2) ? (wid & 1)*64 : 0;
    int rowbase = blockIdx.y * 128;
    int g = lane >> 2, r4 = lane & 3;
    int mq = lane >> 3, r8 = lane & 7;
    uint32_t sA = smem_u32(As_);
    uint32_t sB = smem_u32(Bs_);
    uint32_t offA = ((warp_m + (mq & 1)*8 + r8)*ASTR + (mq >> 1)*4) * 4;
    uint32_t offB = ((warp_n + (mq >> 1)*8 + r8)*ASTR + (mq & 1)*4) * 4;

    float acc[PMT][8][4];
    #pragma unroll
    for (int mt = 0; mt < PMT; mt++)
        #pragma unroll
        for (int nt = 0; nt < 8; nt++)
            #pragma unroll
            for (int q = 0; q < 4; q++) acc[mt][nt][q] = 0.f;

    #define LOAD_PTILE(kt, buf)                                                \
    do {                                                                       \
        int k0 = (kt) * BK;                                                    \
        _Pragma("unroll")                                                      \
        for (int i = 0; i < 4; i++) {                                          \
            int idx = tid + i*128;                                             \
            int rr = idx >> 2, kc = (idx & 3) * 4;                             \
            CPA16P(&As_[buf][rr][kc],                                          \
                   &A[(size_t)(rowbase + rr)*KP + k0 + kc]);                   \
        }                                                                      \
        _Pragma("unroll")                                                      \
        for (int i = 0; i < PBN/32; i++) {                                     \
            int idx = tid + i*128;                                             \
            int rr = idx >> 2, kc = (idx & 3) * 4;                             \
            CPA16P(&Bs_[buf][rr][kc],                                          \
                   &Bt[(size_t)rr*KP + k0 + kc]);                              \
        }                                                                      \
    } while (0)

    LOAD_PTILE(0, 0);
    CP_COMMIT();

    for (int kt = 0; kt < NKP; kt++) {
        int buf = kt & 1;
        if (kt < NKP - 1) {
            LOAD_PTILE(kt + 1, buf ^ 1);
            CP_COMMIT();
            CP_WAIT(1);
        } else {
            CP_WAIT(0);
        }
        __syncthreads();

        uint32_t bA = sA + buf*(128*ASTR*4);
        uint32_t bB = sB + buf*(PBN*ASTR*4);
        #pragma unroll
        for (int ks = 0; ks < 2; ks++) {
            uint32_t af[PMT][4];
            uint32_t bf[8][2];
            #pragma unroll
            for (int mt = 0; mt < PMT; mt++)
                LDSM4(af[mt][0], af[mt][1], af[mt][2], af[mt][3],
                      bA + mt*(16*ASTR*4) + ks*32 + offA);
            #pragma unroll
            for (int p = 0; p < 4; p++)
                LDSM4(bf[2*p][0], bf[2*p][1], bf[2*p+1][0], bf[2*p+1][1],
                      bB + p*(16*ASTR*4) + ks*32 + offB);
            #pragma unroll
            for (int mt = 0; mt < PMT; mt++)
                #pragma unroll
                for (int nt = 0; nt < 8; nt++)
                    MMA_TF32(acc[mt][nt], af[mt], bf[nt]);
        }
        __syncthreads();
    }
    #undef LOAD_PTILE

    // fused epilogue straight from fragments
    #pragma unroll
    for (int mt = 0; mt < PMT; mt++) {
        #pragma unroll
        for (int nt = 0; nt < 8; nt++) {
            int col0 = warp_n + nt*8 + r4*2;
            #pragma unroll
            for (int e = 0; e < 4; e++) {
                int row = rowbase + warp_m + mt*16 + g + (e >> 1)*8;
                int cc  = col0 + (e & 1);
                float v = acc[mt][nt][e];
                int bb = row / NN;
                int n  = row - bb*NN;
                if (MODE == 2) {
                    float s = 1.f/(1.f + expf(-(v + bias[cc])));
                    if (cc < NU) {
                        out[(size_t)((NF + cc)*16 + bb)*NP + n] =
                            rtf32(s * hx[(size_t)bb*HXST + n*NU + cc]);
                    } else {
                        aux[(size_t)bb*HXST + n*NU + (cc - NU)] = s;
                    }
                } else {
                    float cand = tanhf(v + bias[cc]);
                    size_t idx = (size_t)bb*HXST + n*NU + cc;
                    float uu = aux[idx];
                    out[idx] = uu*hx[idx] + (1.f - uu)*cand;
                }
            }
        }
    }
}

// ---------------- launcher ----------------
extern "C" void kernel_launch(void* const* d_in, const int* in_sizes, int n_in,
                              void* d_out, int out_size) {
    const float* in_inputs = (const float*)d_in[0];
    const float* in_hx     = (const float*)d_in[1];
    const float* in_adj    = (const float*)d_in[2];
    const float* in_Wg     = (const float*)d_in[3];
    const float* in_bg     = (const float*)d_in[4];
    const float* in_Wc     = (const float*)d_in[5];
    const float* in_bc     = (const float*)d_in[6];
    float* outp = (float*)d_out;

    float *pS0, *pS1, *pX0, *pX1a, *pX2a, *pX1b, *pX2b, *pXS, *pU, *pWgt, *pWct;
    cudaGetSymbolAddress((void**)&pS0,  g_S0);
    cudaGetSymbolAddress((void**)&pS1,  g_S1);
    cudaGetSymbolAddress((void**)&pX0,  g_X0);
    cudaGetSymbolAddress((void**)&pX1a, g_X1a);
    cudaGetSymbolAddress((void**)&pX2a, g_X2a);
    cudaGetSymbolAddress((void**)&pX1b, g_X1b);
    cudaGetSymbolAddress((void**)&pX2b, g_X2b);
    cudaGetSymbolAddress((void**)&pXS,  g_XS);
    cudaGetSymbolAddress((void**)&pU,   g_u);
    cudaGetSymbolAddress((void**)&pWgt, g_Wgt);
    cudaGetSymbolAddress((void**)&pWct, g_Wct);

    // prep
    deg_row_kernel<<<NP, 256>>>(in_adj);
    deg_col1_kernel<<<dim3(12, 24), 256>>>(in_adj);
    deg_col2_kernel<<<12, 256>>>();
    build_S_kernel<<<dim3(96, 96), dim3(32, 8)>>>(in_adj);
    build_x0_kernel<<<(FP*NP)/256, 256>>>(in_inputs, in_hx);
    pad_W_kernel<<<(192*KP)/256, 256>>>(in_Wg, in_Wc);

    dim3 gG(FP/BN, NP/BM, 2);              // (9, 24, 2) = 432 blocks
    int xsGrid = (NB*NC*NN + 255)/256;
    dim3 gP(1, (NB*NN)/128);               // (1, 375)

    // ---- gate gconv ----
    mma_tf32<0><<<gG, 128>>>(pS0, pX0,  pX1a, nullptr,
                             pS1, pX0,  pX1b, nullptr);
    mma_tf32<1><<<gG, 128>>>(pS0, pX1a, pX2a, pX0,
                             pS1, pX1b, pX2b, pX0);
    materialize_xs_kernel<<<xsGrid, 256>>>();

    // gate projection: sigmoid; writes r*hx into X0t state rows, u into g_u
    mma_proj<2><<<gP, 128>>>(pXS, pWgt, in_bg, in_hx, pU, pX0);

    // ---- candidate gconv (X0t now holds [inputs, r*hx]) ----
    mma_tf32<0><<<gG, 128>>>(pS0, pX0,  pX1a, nullptr,
                             pS1, pX0,  pX1b, nullptr);
    mma_tf32<1><<<gG, 128>>>(pS0, pX1a, pX2a, pX0,
                             pS1, pX1b, pX2b, pX0);
    materialize_xs_kernel<<<xsGrid, 256>>>();

    // candidate projection + tanh + GRU combine -> d_out
    mma_proj<3><<<gP, 128>>>(pXS, pWct, in_bc, in_hx, pU, outp);
}

// round 17
// speedup vs baseline: 1.3383x; 1.1134x over previous
#include <cuda_runtime.h>
#include <math.h>
#include <stdint.h>

// ---------------- problem constants ----------------
#define NN    3000          // nodes
#define NP    3072          // padded nodes (24*128)
#define KDIM  3008          // k extent actually iterated (covers 3000)
#define NF    2             // input feats
#define NU    64            // units
#define NB    16            // batch
#define NC    66            // C = NF + NU
#define FP    1056          // feature rows = NC*NB exactly (11*96)
#define KP    336           // padded gconv K (330 -> 21*16)
#define HXST  (NN*NU)
#define INST  (NN*NF)

// mma tiling (gconv)
#define BM 128
#define BN 96
#define BK 16
#define NKT (KDIM/BK)       // 188
#define ASTR 20             // smem row stride (floats), conflict-free for ldmatrix

// ---------------- static device buffers ----------------
// X feature matrices are stored TRANSPOSED: [FP][NP] (feature-major).
__device__ float g_S0[(size_t)NP*NP];        // tf32-rounded fp32, row-major [m][k]
__device__ float g_S1[(size_t)NP*NP];
__device__ float g_X0 [(size_t)FP*NP];
__device__ float g_X1a[(size_t)FP*NP];
__device__ float g_X2a[(size_t)FP*NP];
__device__ float g_X1b[(size_t)FP*NP];
__device__ float g_X2b[(size_t)FP*NP];
__device__ float g_XS[(size_t)NB*NN*KP];
__device__ float g_u [(size_t)NB*NN*NU];
__device__ float g_Wgt[128*KP];              // W_gate^T [128][KP], tf32-rounded
__device__ float g_Wct[64*KP];               // W_cand^T [64][KP]
__device__ float g_dinv_row[NP];
__device__ float g_dinv_col[NP];
__device__ float g_colpart[24*NP];

// ---------------- helpers ----------------
__device__ __forceinline__ float rtf32(float x) {
    uint32_t u;
    asm("cvt.rna.tf32.f32 %0, %1;" : "=r"(u) : "f"(x));
    return __uint_as_float(u);
}
__device__ __forceinline__ uint32_t smem_u32(const void* p) {
    uint32_t a;
    asm("{ .reg .u64 t; cvta.to.shared.u64 t, %1; cvt.u32.u64 %0, t; }"
        : "=r"(a) : "l"(p));
    return a;
}
#define CPA16P(dst, src) \
    asm volatile("cp.async.cg.shared.global [%0], [%1], 16;" \
                 :: "r"(smem_u32(dst)), "l"(src))
#define CP_COMMIT() asm volatile("cp.async.commit_group;" ::: "memory")
#define CP_WAIT(n)  asm volatile("cp.async.wait_group %0;" :: "n"(n) : "memory")

#define LDSM4(r0, r1, r2, r3, addr) \
    asm volatile("ldmatrix.sync.aligned.m8n8.x4.shared.b16 {%0,%1,%2,%3}, [%4];" \
        : "=r"(r0), "=r"(r1), "=r"(r2), "=r"(r3) : "r"(addr))

#define MMA_TF32(d, a, b) \
    asm volatile( \
        "mma.sync.aligned.m16n8k8.row.col.f32.tf32.tf32.f32 " \
        "{%0,%1,%2,%3}, {%4,%5,%6,%7}, {%8,%9}, {%0,%1,%2,%3};" \
        : "+f"((d)[0]), "+f"((d)[1]), "+f"((d)[2]), "+f"((d)[3]) \
        : "r"((a)[0]), "r"((a)[1]), "r"((a)[2]), "r"((a)[3]), \
          "r"((b)[0]), "r"((b)[1]))

// ---------------- degree kernels ----------------
__global__ void deg_row_kernel(const float* __restrict__ adj) {
    __shared__ float red[256];
    int row = blockIdx.x;
    int tid = threadIdx.x;
    if (row >= NN) { if (tid == 0) g_dinv_row[row] = 0.f; return; }
    float s = 0.f;
    for (int c = tid; c < NN; c += 256) s += adj[(size_t)row*NN + c];
    red[tid] = s; __syncthreads();
    for (int st = 128; st > 0; st >>= 1) {
        if (tid < st) red[tid] += red[tid+st];
        __syncthreads();
    }
    if (tid == 0) {
        float d = red[0];
        g_dinv_row[row] = (d > 0.f) ? 1.f/d : 0.f;
    }
}

__global__ void deg_col1_kernel(const float* __restrict__ adj) {
    int c = blockIdx.x*256 + threadIdx.x;
    int chunk = blockIdx.y;
    if (c >= NN) { if (c < NP) g_colpart[chunk*NP + c] = 0.f; return; }
    int r0 = chunk*125;
    float s = 0.f;
    for (int r = r0; r < r0 + 125; r++) s += adj[(size_t)r*NN + c];
    g_colpart[chunk*NP + c] = s;
}

__global__ void deg_col2_kernel() {
    int c = blockIdx.x*256 + threadIdx.x;
    if (c >= NP) return;
    if (c >= NN) { g_dinv_col[c] = 0.f; return; }
    float s = 0.f;
    #pragma unroll
    for (int k = 0; k < 24; k++) s += g_colpart[k*NP + c];
    g_dinv_col[c] = (s > 0.f) ? 1.f/s : 0.f;
}

// ---------------- build S0/S1 (tf32-rounded fp32, pads zero) ----------------
__global__ void build_S_kernel(const float* __restrict__ adj) {
    __shared__ float sm[32][33];
    int tx = threadIdx.x, ty = threadIdx.y;
    int i0 = blockIdx.y*32, j0 = blockIdx.x*32;
    #pragma unroll
    for (int q = 0; q < 4; q++) {
        int ii = q*8 + ty;
        int gi = i0 + ii, gj = j0 + tx;
        float v = (gi < NN && gj < NN) ? adj[(size_t)gi*NN + gj] : 0.f;
        sm[ii][tx] = v;
        g_S1[(size_t)gi*NP + gj] = rtf32(v * g_dinv_col[gj]);
    }
    __syncthreads();
    #pragma unroll
    for (int q = 0; q < 4; q++) {
        int jj = q*8 + ty;
        g_S0[(size_t)(j0+jj)*NP + (i0+tx)] = rtf32(sm[tx][jj] * g_dinv_row[i0+tx]);
    }
}

// ---------------- build X0 transposed [FP][NP] (tf32-rounded), pads zero ----------------
__global__ void build_x0_kernel(const float* __restrict__ in,
                                const float* __restrict__ hx) {
    int id = blockIdx.x*256 + threadIdx.x;     // FP*NP / 256 exact
    int f = id / NP, n = id % NP;
    int c = f >> 4, b = f & 15;
    float v = 0.f;
    if (n < NN) {
        v = (c < NF) ? in[(size_t)b*INST + n*NF + c]
                     : hx[(size_t)b*HXST + n*NU + (c - NF)];
    }
    g_X0[id] = rtf32(v);
}

// ---------------- pad + transpose weights (tf32-rounded) ----------------
__global__ void pad_W_kernel(const float* __restrict__ Wg,
                             const float* __restrict__ Wc) {
    int id = blockIdx.x*256 + threadIdx.x;     // (128+64)*KP / 256 exact
    if (id < 128*KP) {
        int n = id / KP, k = id % KP;
        g_Wgt[id] = (k < 330) ? rtf32(Wg[k*128 + n]) : 0.f;
    } else {
        int id2 = id - 128*KP;
        int n = id2 / KP, k = id2 % KP;
        g_Wct[id2] = (k < 330) ? rtf32(Wc[k*64 + n]) : 0.f;
    }
}

// ---------------- materialize XS from transposed buffers ----------------
__global__ void materialize_xs_kernel() {
    int id = blockIdx.x*256 + threadIdx.x;
    if (id >= NB*NC*NN) return;
    int n = id % NN;
    int t = id / NN;
    int c = t % NC;
    int b = t / NC;
    size_t src = (size_t)(c*16 + b)*NP + n;
    size_t row = ((size_t)b*NN + n)*KP + c*5;
    g_XS[row+0] = g_X0 [src];
    g_XS[row+1] = g_X1a[src];
    g_XS[row+2] = g_X2a[src];
    g_XS[row+3] = g_X1b[src];
    g_XS[row+4] = g_X2b[src];
}

// ---------------- tf32 mma GEMM, 128x96 tiles, z-fused pairs ----------------
// C^T = (S @ X)^T with X transposed [n(feature)][k(node)].
// MODE1: C = 2*S@X - SUB (SUB transposed layout too).
template<int MODE>
__global__ __launch_bounds__(128, 2)
void mma_tf32(const float* __restrict__ A0, const float* __restrict__ B0,
              float* __restrict__ C0, const float* __restrict__ SUB0,
              const float* __restrict__ A1, const float* __restrict__ B1,
              float* __restrict__ C1, const float* __restrict__ SUB1)
{
    const float* __restrict__ A   = blockIdx.z ? A1   : A0;
    const float* __restrict__ B   = blockIdx.z ? B1   : B0;
    float*       __restrict__ C   = blockIdx.z ? C1   : C0;
    const float* __restrict__ SUB = blockIdx.z ? SUB1 : SUB0;

    __shared__ __align__(16) float smem_all[2*BM*ASTR + 2*BN*ASTR];
    float (*As)[BM][ASTR] = reinterpret_cast<float (*)[BM][ASTR]>(smem_all);
    float (*Bs)[BN][ASTR] = reinterpret_cast<float (*)[BN][ASTR]>(smem_all + 2*BM*ASTR);

    int tid  = threadIdx.x;
    int wid  = tid >> 5, lane = tid & 31;
    int warp_m = (wid >> 1) * 64;
    int warp_n = (wid & 1) * 48;
    int rowbase = blockIdx.y * BM;
    int colbase = blockIdx.x * BN;
    int g = lane >> 2, r4 = lane & 3;

    int mq = lane >> 3, r8 = lane & 7;
    uint32_t sA = smem_u32(smem_all);
    uint32_t sB = sA + 2*BM*ASTR*4;
    uint32_t offA = ((warp_m + (mq & 1)*8 + r8)*ASTR + (mq >> 1)*4) * 4;
    uint32_t offB = ((warp_n + (mq >> 1)*8 + r8)*ASTR + (mq & 1)*4) * 4;

    float acc[4][6][4];
    #pragma unroll
    for (int mt = 0; mt < 4; mt++)
        #pragma unroll
        for (int nt = 0; nt < 6; nt++)
            #pragma unroll
            for (int q = 0; q < 4; q++) acc[mt][nt][q] = 0.f;

    #define LOAD_TILE(kt, buf)                                                 \
    do {                                                                       \
        int k0 = (kt) * BK;                                                    \
        _Pragma("unroll")                                                      \
        for (int i = 0; i < 4; i++) {                                          \
            int idx = tid + i*128;                                             \
            int rr = idx >> 2, kc = (idx & 3) * 4;                             \
            CPA16P(&As[buf][rr][kc],                                           \
                   &A[(size_t)(rowbase + rr)*NP + k0 + kc]);                   \
        }                                                                      \
        _Pragma("unroll")                                                      \
        for (int i = 0; i < 3; i++) {                                          \
            int idx = tid + i*128;                                             \
            int rr = idx >> 2, kc = (idx & 3) * 4;                             \
            CPA16P(&Bs[buf][rr][kc],                                           \
                   &B[(size_t)(colbase + rr)*NP + k0 + kc]);                   \
        }                                                                      \
    } while (0)

    LOAD_TILE(0, 0);
    CP_COMMIT();

    for (int kt = 0; kt < NKT; kt++) {
        int buf = kt & 1;
        if (kt < NKT - 1) {
            LOAD_TILE(kt + 1, buf ^ 1);
            CP_COMMIT();
            CP_WAIT(1);
        } else {
            CP_WAIT(0);
        }
        __syncthreads();

        uint32_t bA = sA + buf*(BM*ASTR*4);
        uint32_t bB = sB + buf*(BN*ASTR*4);
        #pragma unroll
        for (int ks = 0; ks < 2; ks++) {
            uint32_t af[4][4];
            uint32_t bf[6][2];
            #pragma unroll
            for (int mt = 0; mt < 4; mt++)
                LDSM4(af[mt][0], af[mt][1], af[mt][2], af[mt][3],
                      bA + mt*(16*ASTR*4) + ks*32 + offA);
            #pragma unroll
            for (int p = 0; p < 3; p++)
                LDSM4(bf[2*p][0], bf[2*p][1], bf[2*p+1][0], bf[2*p+1][1],
                      bB + p*(16*ASTR*4) + ks*32 + offB);
            #pragma unroll
            for (int mt = 0; mt < 4; mt++)
                #pragma unroll
                for (int nt = 0; nt < 6; nt++)
                    MMA_TF32(acc[mt][nt], af[mt], bf[nt]);
        }
        __syncthreads();
    }
    #undef LOAD_TILE

    // epilogue: transpose through smem, write C^T[n][m] with float4 stores
    // per phase: 48 n-rows x 128 m-floats = 1536 float4s = 12 iters x 128 thr
    float (*st)[132] = reinterpret_cast<float (*)[132]>(smem_all);
    #pragma unroll
    for (int h = 0; h < 2; h++) {
        __syncthreads();
        if ((wid & 1) == h) {
            #pragma unroll
            for (int mt = 0; mt < 4; mt++) {
                int m0 = warp_m + mt*16 + g;
                #pragma unroll
                for (int nt = 0; nt < 6; nt++) {
                    int n0 = nt*8 + r4*2;
                    st[n0  ][m0  ] = acc[mt][nt][0];
                    st[n0+1][m0  ] = acc[mt][nt][1];
                    st[n0  ][m0+8] = acc[mt][nt][2];
                    st[n0+1][m0+8] = acc[mt][nt][3];
                }
            }
        }
        __syncthreads();
        #pragma unroll
        for (int i = 0; i < 12; i++) {
            int idx = tid + i*128;            // 0..1535
            int nn = idx >> 5;                // 0..47
            int mm = (idx & 31) * 4;          // 0..124
            float4 v = *reinterpret_cast<float4*>(&st[nn][mm]);
            size_t off = (size_t)(colbase + h*48 + nn)*NP + rowbase + mm;
            if (MODE == 1) {
                float4 s = *reinterpret_cast<const float4*>(&SUB[off]);
                v.x = 2.f*v.x - s.x; v.y = 2.f*v.y - s.y;
                v.z = 2.f*v.z - s.z; v.w = 2.f*v.w - s.w;
            }
            v.x = rtf32(v.x); v.y = rtf32(v.y);
            v.z = rtf32(v.z); v.w = rtf32(v.w);
            *reinterpret_cast<float4*>(&C[off]) = v;
        }
    }
}

// ---------------- tf32 mma projection GEMM with fused epilogues ----------------
// A = XS [48000][KP] row-major, Bt = W^T [PBN][KP].
// MODE 2: gate (sigmoid; col<64 -> r*hx into X0t state rows; else -> u buffer)
// MODE 3: cand (tanh; out = u*hx + (1-u)*c)
template<int MODE>
__global__ __launch_bounds__(128, 2)
void mma_proj(const float* __restrict__ A,
              const float* __restrict__ Bt,
              const float* __restrict__ bias,
              const float* __restrict__ hx,
              float* __restrict__ aux,
              float* __restrict__ out)
{
    constexpr int PBN = (MODE == 2) ? 128 : 64;
    constexpr int PMT = (MODE == 2) ? 4 : 2;
    constexpr int NKP = KP/BK;   // 21

    __shared__ __align__(16) float As_[2][128][ASTR];
    __shared__ __align__(16) float Bs_[2][PBN][ASTR];

    int tid = threadIdx.x, wid = tid >> 5, lane = tid & 31;
    int warp_m = (MODE == 2) ? (wid >> 1)*64 : wid*32;
    int warp_n = (MODE == 2) ? (wid & 1)*64 : 0;
    int rowbase = blockIdx.y * 128;
    int g = lane >> 2, r4 = lane & 3;
    int mq = lane >> 3, r8 = lane & 7;
    uint32_t sA = smem_u32(As_);
    uint32_t sB = smem_u32(Bs_);
    uint32_t offA = ((warp_m + (mq & 1)*8 + r8)*ASTR + (mq >> 1)*4) * 4;
    uint32_t offB = ((warp_n + (mq >> 1)*8 + r8)*ASTR + (mq & 1)*4) * 4;

    float acc[PMT][8][4];
    #pragma unroll
    for (int mt = 0; mt < PMT; mt++)
        #pragma unroll
        for (int nt = 0; nt < 8; nt++)
            #pragma unroll
            for (int q = 0; q < 4; q++) acc[mt][nt][q] = 0.f;

    #define LOAD_PTILE(kt, buf)                                                \
    do {                                                                       \
        int k0 = (kt) * BK;                                                    \
        _Pragma("unroll")                                                      \
        for (int i = 0; i < 4; i++) {                                          \
            int idx = tid + i*128;                                             \
            int rr = idx >> 2, kc = (idx & 3) * 4;                             \
            CPA16P(&As_[buf][rr][kc],                                          \
                   &A[(size_t)(rowbase + rr)*KP + k0 + kc]);                   \
        }                                                                      \
        _Pragma("unroll")                                                      \
        for (int i = 0; i < PBN/32; i++) {                                     \
            int idx = tid + i*128;                                             \
            int rr = idx >> 2, kc = (idx & 3) * 4;                             \
            CPA16P(&Bs_[buf][rr][kc],                                          \
                   &Bt[(size_t)rr*KP + k0 + kc]);                              \
        }                                                                      \
    } while (0)

    LOAD_PTILE(0, 0);
    CP_COMMIT();

    for (int kt = 0; kt < NKP; kt++) {
        int buf = kt & 1;
        if (kt < NKP - 1) {
            LOAD_PTILE(kt + 1, buf ^ 1);
            CP_COMMIT();
            CP_WAIT(1);
        } else {
            CP_WAIT(0);
        }
        __syncthreads();

        uint32_t bA = sA + buf*(128*ASTR*4);
        uint32_t bB = sB + buf*(PBN*ASTR*4);
        #pragma unroll
        for (int ks = 0; ks < 2; ks++) {
            uint32_t af[PMT][4];
            uint32_t bf[8][2];
            #pragma unroll
            for (int mt = 0; mt < PMT; mt++)
                LDSM4(af[mt][0], af[mt][1], af[mt][2], af[mt][3],
                      bA + mt*(16*ASTR*4) + ks*32 + offA);
            #pragma unroll
            for (int p = 0; p < 4; p++)
                LDSM4(bf[2*p][0], bf[2*p][1], bf[2*p+1][0], bf[2*p+1][1],
                      bB + p*(16*ASTR*4) + ks*32 + offB);
            #pragma unroll
            for (int mt = 0; mt < PMT; mt++)
                #pragma unroll
                for (int nt = 0; nt < 8; nt++)
                    MMA_TF32(acc[mt][nt], af[mt], bf[nt]);
        }
        __syncthreads();
    }
    #undef LOAD_PTILE

    // fused epilogue straight from fragments
    #pragma unroll
    for (int mt = 0; mt < PMT; mt++) {
        #pragma unroll
        for (int nt = 0; nt < 8; nt++) {
            int col0 = warp_n + nt*8 + r4*2;
            #pragma unroll
            for (int e = 0; e < 4; e++) {
                int row = rowbase + warp_m + mt*16 + g + (e >> 1)*8;
                int cc  = col0 + (e & 1);
                float v = acc[mt][nt][e];
                int bb = row / NN;
                int n  = row - bb*NN;
                if (MODE == 2) {
                    float s = 1.f/(1.f + expf(-(v + bias[cc])));
                    if (cc < NU) {
                        out[(size_t)((NF + cc)*16 + bb)*NP + n] =
                            rtf32(s * hx[(size_t)bb*HXST + n*NU + cc]);
                    } else {
                        aux[(size_t)bb*HXST + n*NU + (cc - NU)] = s;
                    }
                } else {
                    float cand = tanhf(v + bias[cc]);
                    size_t idx = (size_t)bb*HXST + n*NU + cc;
                    float uu = aux[idx];
                    out[idx] = uu*hx[idx] + (1.f - uu)*cand;
                }
            }
        }
    }
}

// ---------------- launcher ----------------
extern "C" void kernel_launch(void* const* d_in, const int* in_sizes, int n_in,
                              void* d_out, int out_size) {
    const float* in_inputs = (const float*)d_in[0];
    const float* in_hx     = (const float*)d_in[1];
    const float* in_adj    = (const float*)d_in[2];
    const float* in_Wg     = (const float*)d_in[3];
    const float* in_bg     = (const float*)d_in[4];
    const float* in_Wc     = (const float*)d_in[5];
    const float* in_bc     = (const float*)d_in[6];
    float* outp = (float*)d_out;

    float *pS0, *pS1, *pX0, *pX1a, *pX2a, *pX1b, *pX2b, *pXS, *pU, *pWgt, *pWct;
    cudaGetSymbolAddress((void**)&pS0,  g_S0);
    cudaGetSymbolAddress((void**)&pS1,  g_S1);
    cudaGetSymbolAddress((void**)&pX0,  g_X0);
    cudaGetSymbolAddress((void**)&pX1a, g_X1a);
    cudaGetSymbolAddress((void**)&pX2a, g_X2a);
    cudaGetSymbolAddress((void**)&pX1b, g_X1b);
    cudaGetSymbolAddress((void**)&pX2b, g_X2b);
    cudaGetSymbolAddress((void**)&pXS,  g_XS);
    cudaGetSymbolAddress((void**)&pU,   g_u);
    cudaGetSymbolAddress((void**)&pWgt, g_Wgt);
    cudaGetSymbolAddress((void**)&pWct, g_Wct);

    // prep
    deg_row_kernel<<<NP, 256>>>(in_adj);
    deg_col1_kernel<<<dim3(12, 24), 256>>>(in_adj);
    deg_col2_kernel<<<12, 256>>>();
    build_S_kernel<<<dim3(96, 96), dim3(32, 8)>>>(in_adj);
    build_x0_kernel<<<(FP*NP)/256, 256>>>(in_inputs, in_hx);
    pad_W_kernel<<<(192*KP)/256, 256>>>(in_Wg, in_Wc);

    dim3 gG(FP/BN, NP/BM, 2);              // (11, 24, 2) = 528 blocks
    int xsGrid = (NB*NC*NN + 255)/256;
    dim3 gP(1, (NB*NN)/128);               // (1, 375)

    // ---- gate gconv ----
    mma_tf32<0><<<gG, 128>>>(pS0, pX0,  pX1a, nullptr,
                             pS1, pX0,  pX1b, nullptr);
    mma_tf32<1><<<gG, 128>>>(pS0, pX1a, pX2a, pX0,
                             pS1, pX1b, pX2b, pX0);
    materialize_xs_kernel<<<xsGrid, 256>>>();

    // gate projection: sigmoid; writes r*hx into X0t state rows, u into g_u
    mma_proj<2><<<gP, 128>>>(pXS, pWgt, in_bg, in_hx, pU, pX0);

    // ---- candidate gconv (X0t now holds [inputs, r*hx]) ----
    mma_tf32<0><<<gG, 128>>>(pS0, pX0,  pX1a, nullptr,
                             pS1, pX0,  pX1b, nullptr);
    mma_tf32<1><<<gG, 128>>>(pS0, pX1a, pX2a, pX0,
                             pS1, pX1b, pX2b, pX0);
    materialize_xs_kernel<<<xsGrid, 256>>>();

    // candidate projection + tanh + GRU combine -> d_out
    mma_proj<3><<<gP, 128>>>(pXS, pWct, in_bc, in_hx, pU, outp);
}